// round 16
// baseline (speedup 1.0000x reference)
#include <cuda_runtime.h>
#include <cuda_bf16.h>
#include <cstdint>

// Problem shape (fixed by the dataset's setup_inputs()).
static constexpr int B = 8;
static constexpr int T = 256;
static constexpr int U = 65;     // acts U dim; labels array is U-1 long
static constexpr int V = 1024;

// DP wavefront tiling: warps 0..2 each own OWN cells + NDIAG-cell left halo.
static constexpr int NDIAG = 8;          // diagonals per barrier period
static constexpr int OWN   = 32 - NDIAG; // 24 owned cells per warp
static constexpr int NWARP = 3;          // 3*24 = 72 cells >= U=65
static constexpr int DPTHREADS = 32 * NWARP;   // 96

static constexpr int ROWS_PER_BLK = 8;   // lse rows per block

// Producer->consumer pacing granularity: chunks of CHUNK_T t-rows.
static constexpr int CHUNK_T  = 16;
static constexpr int NCHUNK   = T / CHUNK_T;        // 16 chunks per batch
static constexpr int CHUNK_EXP = CHUNK_T * U;       // 1040 warp-releases/chunk

static constexpr float LOG2E_F = 1.4426950408889634f;
static constexpr float LN2_F   = 0.6931471805599453f;

// Scratch (device globals; no allocation allowed in kernel_launch).
__device__ float2 g_pk[B * T * U];     // {lp_blank, lp_label} * log2e at (b,t,u)
__device__ float  g_ll[B];             // per-batch log-likelihood (nat log)
__device__ int    g_cnt[B * NCHUNK];   // per-(b,chunk) row counters (dp resets)
__device__ int    g_done;              // finalize counter (winner resets)

// ---- message-passing primitives ----
__device__ __forceinline__ int ld_acquire_gpu(const int* p) {
    int v;
    asm volatile("ld.acquire.gpu.global.b32 %0, [%1];" : "=r"(v) : "l"(p) : "memory");
    return v;
}
__device__ __forceinline__ void red_release_gpu(int* p, int v) {
    asm volatile("red.release.gpu.global.add.u32 [%0], %1;" :: "l"(p), "r"(v) : "memory");
}
__device__ __forceinline__ float ex2f(float x) {
    float r; asm("ex2.approx.ftz.f32 %0, %1;" : "=f"(r) : "f"(x)); return r;
}
__device__ __forceinline__ float lg2f(float x) {
    float r; asm("lg2.approx.ftz.f32 %0, %1;" : "=f"(r) : "f"(x)); return r;
}
// log2-domain logaddexp: no ln<->log2 FMULs on the critical chain.
__device__ __forceinline__ float laddexp2(float x, float y) {
    const float m = fmaxf(x, y);
    return m + lg2f(1.0f + ex2f(-fabsf(x - y)));
}

// ---------------------------------------------------------------------------
// Fused kernel. Blocks 0..B-1: dp role (paced by per-chunk counters, reading
// g_pk from L2 with one-period-ahead prefetch). Blocks B..: lse role, rows in
// T-MAJOR order across batches so all 8 dp blocks advance with the lse wave.
// ---------------------------------------------------------------------------
__global__ __launch_bounds__(256) void fused_kernel(
    const float* __restrict__ acts,
    const int*   __restrict__ labels,
    const int*   __restrict__ act_lens,
    const int*   __restrict__ label_lens,
    float*       __restrict__ out)
{
    __shared__ float s_a0[U];                    // alpha(0,u)
    __shared__ float s_tmp[U];                   // t=0 label row
    __shared__ float s_edge[2 * NWARP * NDIAG];  // parity double buffer
    __shared__ float s_res;

    if (blockIdx.x >= B) {
        // ================= lse role =================
        const int warp = threadIdx.x >> 5;
        const int lane = threadIdx.x & 31;
        const int r    = (blockIdx.x - B) * ROWS_PER_BLK + warp;

        // T-major decode: r -> (t, b, u). Earlier t => earlier block => all dp
        // blocks are fed in wavefront order.
        const int t   = r / (B * U);
        const int rem = r - t * (B * U);
        const int b   = rem / U;
        const int u   = rem - b * U;
        const int gidx = (b * T + t) * U + u;          // canonical (b,t,u) flat

        const bool skip = (t >= act_lens[b]) || (u > label_lens[b]);
        if (!skip) {
            int lab = 0, lab_lane = -1, lab_i = 0, lab_r = 0;
            const bool has_lab = (u < U - 1);
            if (has_lab) {
                lab      = labels[b * (U - 1) + u];
                lab_lane = (lab >> 2) & 31;
                lab_i    = lab >> 7;
                lab_r    = lab & 3;
            }

            const float4* row =
                reinterpret_cast<const float4*>(acts) + (size_t)gidx * (V / 4);

            float4 v[8];
            #pragma unroll
            for (int i = 0; i < 8; ++i) v[i] = __ldcs(row + i * 32 + lane);

            float labv = 0.0f;
            float s0 = 0.f, s1 = 0.f, s2 = 0.f, s3 = 0.f;
            #pragma unroll
            for (int i = 0; i < 8; ++i) {
                s0 += __expf(v[i].x);
                s1 += __expf(v[i].y);
                s2 += __expf(v[i].z);
                s3 += __expf(v[i].w);
                if (has_lab && lane == lab_lane && i == lab_i) {
                    labv = (lab_r == 0) ? v[i].x : (lab_r == 1) ? v[i].y
                         : (lab_r == 2) ? v[i].z : v[i].w;
                }
            }
            float s = (s0 + s1) + (s2 + s3);
            #pragma unroll
            for (int o = 16; o; o >>= 1) s += __shfl_xor_sync(0xffffffffu, s, o);

            const float lse = __logf(s);
            const float blank_all = __shfl_sync(0xffffffffu, v[0].x, 0);

            if (has_lab) {
                if (lane == lab_lane)
                    g_pk[gidx] = make_float2((blank_all - lse) * LOG2E_F,
                                             (labv      - lse) * LOG2E_F);
            } else if (lane == 0) {
                g_pk[gidx] = make_float2((blank_all - lse) * LOG2E_F, 0.0f);
            }
            // FastEmit scaling is the identity in the forward pass -> dropped.
        }
        // Per-warp release: this row is published (sync gives cumulativity).
        __syncwarp(0xffffffffu);
        if (lane == 0)
            red_release_gpu(&g_cnt[b * NCHUNK + (t >> 4)], 1);
        return;
    }

    // ================= dp role (block b = blockIdx.x) =================
    const int b = blockIdx.x;
    if (threadIdx.x >= DPTHREADS) return;
    const int tid  = threadIdx.x;
    const int lane = tid & 31;
    const int warp = tid >> 5;

    const int Tb   = act_lens[b];
    const int Ub   = label_lens[b] + 1;
    const int base = b * (T * U);
    int* const cnt = &g_cnt[b * NCHUNK];

    // Wait for chunk 0 (rows t in [0,16)): covers the t=0 cumsum and the
    // period-0 prefetch (rows <= NDIAG-1 = 7) AND period 0's nxt prefetch
    // (rows <= 2*NDIAG-2 = 14).
    if (tid == 0) {
        while (ld_acquire_gpu(&cnt[0]) < CHUNK_EXP) __nanosleep(64);
    }
    asm volatile("bar.sync 1, %0;" :: "n"(DPTHREADS) : "memory");

    // t = 0 row: alpha(0,u) = cumsum of lpl2[b,0,0..u-1].
    if (tid < U - 1) s_tmp[tid] = g_pk[base + tid].y;
    asm volatile("bar.sync 1, %0;" :: "n"(DPTHREADS) : "memory");
    if (tid == 0) {
        s_a0[0] = 0.0f;
        float rr = 0.0f;
        for (int uu = 1; uu < U; ++uu) { rr += s_tmp[uu - 1]; s_a0[uu] = rr; }
    }
    asm volatile("bar.sync 1, %0;" :: "n"(DPTHREADS) : "memory");

    const int  u     = OWN * warp - NDIAG + lane;   // cell index of this lane
    const bool is_u0 = (u == 0);
    float a = (u >= 0 && u < U) ? s_a0[u] : 0.0f;

    int lo; unsigned span;
    if (u >= 0 && u < Ub) { lo = u + 1; span = (unsigned)(Tb - 2); }
    else                  { lo = 1 << 30; span = 0; }

    // Running flat index: pos(d) = base + (d-u-1)*U + u; at d=1 -> base-(U-1)u.
    int idxi = base - (U - 1) * u;
    const unsigned IMAX = (unsigned)(B * T * U - 1);

    // Prefetch period 0 into registers (induction-only addresses).
    float2 cur[NDIAG];
    #pragma unroll
    for (int j = 0; j < NDIAG; ++j)
        cur[j] = g_pk[min((unsigned)(idxi + j * U), IMAX)];
    idxi += NDIAG * U;

    if (lane >= OWN) s_edge[NWARP * NDIAG + warp * NDIAG + (lane - OWN)] = a;
    asm volatile("bar.sync 1, %0;" :: "n"(DPTHREADS) : "memory");

    const int dmax = (Tb - 1) + (Ub - 1);
    const int nper = (dmax + NDIAG - 1) / NDIAG;

    int ready = 0;                 // highest chunk known complete (tid0 only)
    for (int p = 0; p < nper; ++p) {
        const int d0 = 1 + p * NDIAG;

        // Pace: this period prefetches rows up to d0 + 2*NDIAG - 2.
        if (tid == 0) {
            const int need = min(d0 + 2 * NDIAG - 2, Tb - 1) >> 4;
            while (ready < need) {
                if (ld_acquire_gpu(&cnt[ready + 1]) >= CHUNK_EXP) ++ready;
                else __nanosleep(64);
            }
        }
        asm volatile("bar.sync 1, %0;" :: "n"(DPTHREADS) : "memory");

        // Halo reload from the left warp's end-of-previous-period values.
        if (warp > 0 && lane < NDIAG)
            a = s_edge[((p + 1) & 1) * (NWARP * NDIAG) + (warp - 1) * NDIAG + lane];

        // Prefetch next period (independent of a; hides L2 latency).
        float2 nxt[NDIAG];
        #pragma unroll
        for (int j = 0; j < NDIAG; ++j)
            nxt[j] = g_pk[min((unsigned)(idxi + j * U), IMAX)];

        #pragma unroll
        for (int j = 0; j < NDIAG; ++j) {
            const int d = d0 + j;
            const float z = a + cur[j].y;                 // for right neighbor
            const float x = a + cur[j].x;                 // from (t-1, u)
            const float znb = __shfl_up_sync(0xffffffffu, z, 1);
            const float vv = is_u0 ? x : laddexp2(x, znb);
            if ((unsigned)(d - lo) <= span) a = vv;
        }

        #pragma unroll
        for (int j = 0; j < NDIAG; ++j) cur[j] = nxt[j];
        idxi += NDIAG * U;

        if (lane >= OWN)
            s_edge[(p & 1) * (NWARP * NDIAG) + warp * NDIAG + (lane - OWN)] = a;
        asm volatile("bar.sync 1, %0;" :: "n"(DPTHREADS) : "memory");
    }

    // Owned copy of cell Ub-1 records the log-likelihood (back to nat log).
    if (u == Ub - 1 && lane >= NDIAG) {
        const float lpb_last = g_pk[base + (Tb - 1) * U + u].x;
        s_res = (a + lpb_last) * LN2_F;
    }
    asm volatile("bar.sync 1, %0;" :: "n"(DPTHREADS) : "memory");

    if (tid == 0) {
        g_ll[b] = s_res;
        __threadfence();

        // Drain remaining chunks (all 1040 arrivals observed) then reset the
        // counters for the next graph replay — safe: no further REDs can be
        // in flight once the count is full.
        for (int k = 0; k < NCHUNK; ++k) {
            while (ld_acquire_gpu(&cnt[k]) < CHUNK_EXP) __nanosleep(256);
            cnt[k] = 0;
        }

        // Fused finalize: last dp block sums the 8 costs in fixed order.
        if (atomicAdd(&g_done, 1) == B - 1) {
            __threadfence();
            float ssum = 0.0f;
            #pragma unroll
            for (int i = 0; i < B; ++i)
                ssum += -((volatile float*)g_ll)[i];
            out[0] = ssum * (1.0f / (float)B);
            g_done = 0;                         // reset for the next replay
        }
    }
}

// ---------------------------------------------------------------------------
extern "C" void kernel_launch(void* const* d_in, const int* in_sizes, int n_in,
                              void* d_out, int out_size)
{
    const float* acts       = (const float*)d_in[0];
    const int*   labels     = (const int*)d_in[1];
    const int*   act_lens   = (const int*)d_in[2];
    const int*   label_lens = (const int*)d_in[3];
    float*       out        = (float*)d_out;

    // 8 dp blocks first (resident from wave 1), then 16640 lse blocks in
    // t-major order so every dp block is fed in wavefront order.
    const int grid = B + (B * T * U) / ROWS_PER_BLK;
    fused_kernel<<<grid, 256>>>(acts, labels, act_lens, label_lens, out);
}